// round 12
// baseline (speedup 1.0000x reference)
#include <cuda_runtime.h>
#include <math.h>

constexpr int N_OSC  = 2048;
constexpr int N_SAMP = 16384;
constexpr int LAT    = 32;
constexpr int HALF   = N_OSC * LAT;               // 65536

constexpr int OSC_CHUNK  = 32;
constexpr int PAIRS      = OSC_CHUNK / 2;          // 16 oscillator pairs
constexpr int KENT       = LAT + 2;                // 32 segs + pre(32) + post(33)
constexpr int SAMP_CHUNK = 1024;
constexpr int THREADS    = 256;
constexpr int SPT        = 4;
constexpr int N_OSC_BLK  = N_OSC / OSC_CHUNK;      // 64
constexpr int N_SAMP_BLK = N_SAMP / SAMP_CHUNK;    // 16

// Packed f32x2 ops (FFMA2/FADD2/FMUL2: sm_10x-only, PTX-only)
#define FMA2(d,a,b,c) asm("fma.rn.f32x2 %0,%1,%2,%3;" : "=l"(d) : "l"(a), "l"(b), "l"(c))
#define ADD2(d,a,b)   asm("add.rn.f32x2 %0,%1,%2;"    : "=l"(d) : "l"(a), "l"(b))
#define MUL2(d,a,b)   asm("mul.rn.f32x2 %0,%1,%2;"    : "=l"(d) : "l"(a), "l"(b))
#define PACK2(d,lo,hi)   asm("mov.b64 %0,{%1,%2};" : "=l"(d) : "f"(lo), "f"(hi))
#define UNPACK2(lo,hi,v) asm("mov.b64 {%0,%1},%2;" : "=f"(lo), "=f"(hi) : "l"(v))

// Partial signals per oscillator block: 64 x 16384 floats = 4 MB
__device__ float    g_scratch[N_OSC_BLK * N_SAMP];
// Arrival counters (atomicInc wraps 63->0: graph-replay safe)
__device__ unsigned g_cnt[N_SAMP_BLK];

// sin(2*pi*r), r in [-0.5,0.5]: degree-9 odd Chebyshev poly (max err ~3e-5)
constexpr float SA1 =  6.2831008f;
constexpr float SA3 = -41.332240f;
constexpr float SA5 =  81.374886f;
constexpr float SA7 = -74.511488f;
constexpr float SA9 =  32.841421f;
constexpr float MAGIC = 12582912.0f;               // 1.5 * 2^23 (round-to-int)

// -----------------------------------------------------------------------------
// SINGLE fused kernel. Block = 16 oscillator PAIRS x 1024 samples.
// NO MUFU in the main loop: sin computed as packed polynomial on the FMA pipe
// (R11 evidence: MUFU/sin is the fixed-rate bottleneck; all other pipes <30%).
//
// Phase (cycles): u = c1*(fp + c1*df/512) + bu,  bu = (C_k mod 2)/2
//   segment k: c1 = (m+1)/2;  pre (entry 32): c1 = (i-255)/2, df=da=0
//   post (entry 33): c1 = (i-16127)/2, df=da=0   -> loop is branch-free
// amp = apadj + c1*da/256  (apadj = ap - da/1024; pre/post have da=0 -> exact ap)
// r = u - rint(u) via magic-number add/sub (exact, FMA pipe, no CVT)
// -> 13 packed FMA-class ops per pair-sample.
// -----------------------------------------------------------------------------
__global__ __launch_bounds__(THREADS, 4)
void osc_kernel(const float* __restrict__ latent, float* __restrict__ out) {
    __shared__ float4 s_fd[PAIRS * KENT];   // (fp_e, fp_o, df512_e, df512_o)
    __shared__ float4 s_ad[PAIRS * KENT];   // (da256_e, da256_o, apadj_e, apadj_o)
    __shared__ float2 s_bu[PAIRS * KENT];   // (bu_e, bu_o)
    __shared__ unsigned s_old;

    const int tid  = threadIdx.x;
    const int lane = tid & 31;
    const int warp = tid >> 5;
    const int oscBase = blockIdx.y * OSC_CHUNK;

    // ---- phase 0: |latent| passthrough ----
    if (tid < 32) {
        const int idx = ((blockIdx.y * N_SAMP_BLK + blockIdx.x) * 32 + tid) * 4;
        const int src = (idx < HALF) ? (HALF + idx) : (idx - HALF);
        const float4 v = *reinterpret_cast<const float4*>(&latent[src]);
        *reinterpret_cast<float4*>(&out[N_SAMP + idx]) =
            make_float4(fabsf(v.x), fabsf(v.y), fabsf(v.z), fabsf(v.w));
    }

    // ---- phase 1: fp32 warp-scan prologue, pair-interleaved tables ----
    float* fdp = reinterpret_cast<float*>(s_fd);
    float* adp = reinterpret_cast<float*>(s_ad);
    float* bup = reinterpret_cast<float*>(s_bu);
#pragma unroll
    for (int j = 0; j < OSC_CHUNK / 8; ++j) {
        const int o   = warp * (OSC_CHUNK / 8) + j;
        const int q   = o >> 1;
        const int par = o & 1;
        const int go  = oscBase + o;
        const float f  = fabsf(latent[(size_t)(N_OSC + go) * LAT + lane]);
        const float a  = fabsf(latent[(size_t)go * LAT + lane]);
        const float fn = __shfl_down_sync(0xffffffffu, f, 1);
        const float an = __shfl_down_sync(0xffffffffu, a, 1);
        const float df = (lane < 31) ? (fn - f) : 0.0f;
        const float da = (lane < 31) ? (an - a) : 0.0f;
        const float t = (lane < 31) ? 256.0f * (f + fn) : 0.0f;
        float sc = t;
#pragma unroll
        for (int d = 1; d < 32; d <<= 1) {
            const float u = __shfl_up_sync(0xffffffffu, sc, d);
            if (lane >= d) sc += u;
        }
        const float f0 = __shfl_sync(0xffffffffu, f, 0);
        const float C  = fmaf(256.0f, f0, sc - t);        // exclusive prefix C_k
        const float r  = fmaf(-2.0f, rintf(0.5f * C), C); // C mod 2, exact
        const float bu = 0.5f * r;                        // in cycles
        const int e = q * KENT + lane;
        fdp[4*e + par]     = f;
        fdp[4*e + 2 + par] = df * (1.0f / 512.0f);
        adp[4*e + par]     = da * (1.0f / 256.0f);
        adp[4*e + 2 + par] = fmaf(da, -0.0009765625f, a); // ap - da/1024
        bup[2*e + par]     = bu;
        if (lane == 0) {                                  // pre entry (k=32)
            const int e2 = q * KENT + 32;
            fdp[4*e2 + par] = f;  fdp[4*e2 + 2 + par] = 0.0f;
            adp[4*e2 + par] = 0.0f; adp[4*e2 + 2 + par] = a;
            bup[2*e2 + par] = bu;
        }
        if (lane == 31) {                                 // post entry (k=33)
            const int e3 = q * KENT + 33;
            fdp[4*e3 + par] = f;  fdp[4*e3 + 2 + par] = 0.0f;
            adp[4*e3 + par] = 0.0f; adp[4*e3 + 2 + par] = a;
            bup[2*e3 + par] = bu;
        }
    }
    __syncthreads();

    // ---- per-thread sample constants: just k and c1[s] ----
    const int i0 = blockIdx.x * SAMP_CHUNK + tid * SPT;
    int k;
    float c1[SPT];
    if (i0 < 256) {
        k = 32;
#pragma unroll
        for (int s = 0; s < SPT; ++s) c1[s] = 0.5f * (float)(i0 + s - 255);
    } else if (i0 >= 16128) {
        k = 33;
#pragma unroll
        for (int s = 0; s < SPT; ++s) c1[s] = 0.5f * (float)(i0 + s - 16127);
    } else {
        k = (i0 - 256) >> 9;
        const int m0 = (i0 - 256) & 511;
#pragma unroll
        for (int s = 0; s < SPT; ++s) c1[s] = 0.5f * (float)(m0 + s + 1);
    }

    unsigned long long c1p[SPT], acc2[SPT];
    unsigned long long a1p, a3p, a5p, a7p, a9p, mgp, nmgp, non;
    PACK2(a1p, SA1, SA1);  PACK2(a3p, SA3, SA3);  PACK2(a5p, SA5, SA5);
    PACK2(a7p, SA7, SA7);  PACK2(a9p, SA9, SA9);
    PACK2(mgp, MAGIC, MAGIC);  PACK2(nmgp, -MAGIC, -MAGIC);
    PACK2(non, -1.0f, -1.0f);
#pragma unroll
    for (int s = 0; s < SPT; ++s) { PACK2(c1p[s], c1[s], c1[s]); acc2[s] = 0ull; }

    // ---- phase 2: packed polynomial main loop (no MUFU) ----
    const float4* fk = &s_fd[k];
    const float4* ak = &s_ad[k];
    const float2* bk = &s_bu[k];
#pragma unroll 4
    for (int q = 0; q < PAIRS; ++q) {
        const float4 fd = fk[q * KENT];    // (fp_e, fp_o, df512_e, df512_o)
        const float4 ad = ak[q * KENT];    // (da256_e, da256_o, apadj_e, apadj_o)
        const float2 b2 = bk[q * KENT];
        unsigned long long fp2, df2, dc2, aa2, bu2;
        PACK2(fp2, fd.x, fd.y);
        PACK2(df2, fd.z, fd.w);
        PACK2(dc2, ad.x, ad.y);
        PACK2(aa2, ad.z, ad.w);
        PACK2(bu2, b2.x, b2.y);
#pragma unroll
        for (int s = 0; s < SPT; ++s) {
            unsigned long long t, u, tm, ri, r, z, h, sv, amp;
            FMA2(t,  c1p[s], df2, fp2);    // fp + c1*df/512
            FMA2(u,  c1p[s], t,   bu2);    // u = c1*(...) + bu   (cycles)
            ADD2(tm, u, mgp);              // round-to-nearest-int via magic
            ADD2(ri, tm, nmgp);            // ri = rint(u)
            FMA2(r,  ri, non, u);          // r = u - ri,  exact, in [-0.5,0.5]
            MUL2(z,  r, r);
            FMA2(h,  z, a9p, a7p);         // Horner: sin(2*pi*r)/r
            FMA2(h,  h, z, a5p);
            FMA2(h,  h, z, a3p);
            FMA2(h,  h, z, a1p);
            MUL2(sv, h, r);                // sin
            FMA2(amp, c1p[s], dc2, aa2);   // apadj + c1*da/256
            FMA2(acc2[s], sv, amp, acc2[s]);
        }
    }

    float acc[SPT];
#pragma unroll
    for (int s = 0; s < SPT; ++s) {
        float lo, hi;
        UNPACK2(lo, hi, acc2[s]);
        acc[s] = lo + hi;
    }
    *reinterpret_cast<float4*>(&g_scratch[blockIdx.y * N_SAMP + i0]) =
        make_float4(acc[0], acc[1], acc[2], acc[3]);

    // ---- phase 3: last block per column reduces (fixed order = deterministic) ----
    __threadfence();
    __syncthreads();
    if (tid == 0)
        s_old = atomicInc(&g_cnt[blockIdx.x], N_OSC_BLK - 1);   // wraps 63 -> 0
    __syncthreads();

    if (s_old == N_OSC_BLK - 1) {
        __threadfence();
        const int j0 = blockIdx.x * SAMP_CHUNK + tid * 4;
        float4 a0 = make_float4(0.f, 0.f, 0.f, 0.f);
        float4 a1 = a0;
#pragma unroll
        for (int b = 0; b < N_OSC_BLK; b += 2) {
            const float4 v0 = *reinterpret_cast<const float4*>(&g_scratch[(b + 0) * N_SAMP + j0]);
            const float4 v1 = *reinterpret_cast<const float4*>(&g_scratch[(b + 1) * N_SAMP + j0]);
            a0.x += v0.x; a0.y += v0.y; a0.z += v0.z; a0.w += v0.w;
            a1.x += v1.x; a1.y += v1.y; a1.z += v1.z; a1.w += v1.w;
        }
        const float sc = 1.0f / (float)N_OSC;
        *reinterpret_cast<float4*>(&out[j0]) = make_float4(
            (a0.x + a1.x) * sc, (a0.y + a1.y) * sc,
            (a0.z + a1.z) * sc, (a0.w + a1.w) * sc);
    }
}

extern "C" void kernel_launch(void* const* d_in, const int* in_sizes, int n_in,
                              void* d_out, int out_size) {
    const float* latent = (const float*)d_in[n_in - 1];
    for (int i = 0; i < n_in; ++i) {
        if (in_sizes[i] == 2 * HALF) { latent = (const float*)d_in[i]; break; }
    }
    float* out = (float*)d_out;

    dim3 grid(N_SAMP_BLK, N_OSC_BLK);                       // 16 x 64 = 1024 blocks
    osc_kernel<<<grid, THREADS>>>(latent, out);
}

// round 13
// speedup vs baseline: 1.1089x; 1.1089x over previous
#include <cuda_runtime.h>
#include <math.h>

constexpr int N_OSC  = 2048;
constexpr int N_SAMP = 16384;
constexpr int LAT    = 32;
constexpr int HALF   = N_OSC * LAT;               // 65536

constexpr int OSC_CHUNK  = 32;
constexpr int PAIRS      = OSC_CHUNK / 2;          // 16: pairs 0-7 poly, 8-15 mufu
constexpr int HPAIRS     = PAIRS / 2;              // 8
constexpr int KENT       = LAT + 2;                // 32 segs + pre(32) + post(33)
constexpr int SAMP_CHUNK = 1024;
constexpr int THREADS    = 256;
constexpr int SPT        = 4;
constexpr int N_OSC_BLK  = N_OSC / OSC_CHUNK;      // 64
constexpr int N_SAMP_BLK = N_SAMP / SAMP_CHUNK;    // 16

// Packed f32x2 ops (sm_10x-only, PTX-only)
#define FMA2(d,a,b,c) asm("fma.rn.f32x2 %0,%1,%2,%3;" : "=l"(d) : "l"(a), "l"(b), "l"(c))
#define ADD2(d,a,b)   asm("add.rn.f32x2 %0,%1,%2;"    : "=l"(d) : "l"(a), "l"(b))
#define MUL2(d,a,b)   asm("mul.rn.f32x2 %0,%1,%2;"    : "=l"(d) : "l"(a), "l"(b))
#define PACK2(d,lo,hi)   asm("mov.b64 %0,{%1,%2};" : "=l"(d) : "f"(lo), "f"(hi))
#define UNPACK2(lo,hi,v) asm("mov.b64 {%0,%1},%2;" : "=f"(lo), "=f"(hi) : "l"(v))

__device__ float    g_scratch[N_OSC_BLK * N_SAMP];   // 4 MB partials
__device__ unsigned g_cnt[N_SAMP_BLK];               // wraps 63->0: replay-safe

// sin(2*pi*r), r in [-0.5,0.5]: degree-9 odd poly (max err ~3e-5)
constexpr float SA1 =  6.2831008f;
constexpr float SA3 = -41.332240f;
constexpr float SA5 =  81.374886f;
constexpr float SA7 = -74.511488f;
constexpr float SA9 =  32.841421f;
constexpr float MAGIC  = 12582912.0f;                // 1.5 * 2^23
constexpr float TWOPI_F = 6.28318530717958648f;

// -----------------------------------------------------------------------------
// HYBRID kernel: per block, 8 oscillator pairs go through the packed FFMA2
// polynomial (FMA pipe) and 8 pairs through scalar __sinf (MUFU/XU pipe),
// interleaved per loop iteration so both pipes run concurrently.
// (R11: mufu-only saturates XU at 18.5us with FMA 26% idle;
//  R12: poly-only is FFMA2 latency-bound at 26us with XU idle.)
//
// Tables (pair-interleaved, KENT entries incl. pre/post rows -> branch-free):
//   poly pairs store u in CYCLES;  mufu pairs pre-scaled by 2*pi (radians).
//   u/Q = c1*(v + c1*dv) + b;  amp = apadj + c1*dac;  c1 = half-index.
// -----------------------------------------------------------------------------
__global__ __launch_bounds__(THREADS, 4)
void osc_kernel(const float* __restrict__ latent, float* __restrict__ out) {
    __shared__ float4 s_fd[PAIRS * KENT];   // (v_e, v_o, dv_e, dv_o)
    __shared__ float4 s_ad[PAIRS * KENT];   // (dac_e, dac_o, apadj_e, apadj_o)
    __shared__ float2 s_bu[PAIRS * KENT];   // (b_e, b_o)
    __shared__ unsigned s_old;

    const int tid  = threadIdx.x;
    const int lane = tid & 31;
    const int warp = tid >> 5;
    const int oscBase = blockIdx.y * OSC_CHUNK;

    // ---- phase 0: |latent| passthrough ----
    if (tid < 32) {
        const int idx = ((blockIdx.y * N_SAMP_BLK + blockIdx.x) * 32 + tid) * 4;
        const int src = (idx < HALF) ? (HALF + idx) : (idx - HALF);
        const float4 v = *reinterpret_cast<const float4*>(&latent[src]);
        *reinterpret_cast<float4*>(&out[N_SAMP + idx]) =
            make_float4(fabsf(v.x), fabsf(v.y), fabsf(v.z), fabsf(v.w));
    }

    // ---- phase 1: fp32 warp-scan prologue ----
    float* fdp = reinterpret_cast<float*>(s_fd);
    float* adp = reinterpret_cast<float*>(s_ad);
    float* bup = reinterpret_cast<float*>(s_bu);
#pragma unroll
    for (int j = 0; j < OSC_CHUNK / 8; ++j) {
        const int o   = warp * (OSC_CHUNK / 8) + j;
        const int q   = o >> 1;
        const int par = o & 1;
        const int go  = oscBase + o;
        const float f  = fabsf(latent[(size_t)(N_OSC + go) * LAT + lane]);
        const float a  = fabsf(latent[(size_t)go * LAT + lane]);
        const float fn = __shfl_down_sync(0xffffffffu, f, 1);
        const float an = __shfl_down_sync(0xffffffffu, a, 1);
        const float df = (lane < 31) ? (fn - f) : 0.0f;
        const float da = (lane < 31) ? (an - a) : 0.0f;
        const float t = (lane < 31) ? 256.0f * (f + fn) : 0.0f;
        float sc = t;
#pragma unroll
        for (int d = 1; d < 32; d <<= 1) {
            const float u = __shfl_up_sync(0xffffffffu, sc, d);
            if (lane >= d) sc += u;
        }
        const float f0 = __shfl_sync(0xffffffffu, f, 0);
        const float C  = fmaf(256.0f, f0, sc - t);        // exclusive prefix C_k
        const float r  = fmaf(-2.0f, rintf(0.5f * C), C); // C mod 2, exact
        // pairs >= HPAIRS take the mufu path: pre-scale phase terms by 2*pi
        const float S  = (q >= HPAIRS) ? TWOPI_F : 1.0f;
        const float vf = S * f;
        const float dv = S * (df * (1.0f / 512.0f));
        const float bu = S * (0.5f * r);
        const int e = q * KENT + lane;
        fdp[4*e + par]     = vf;
        fdp[4*e + 2 + par] = dv;
        adp[4*e + par]     = da * (1.0f / 256.0f);
        adp[4*e + 2 + par] = fmaf(da, -0.0009765625f, a); // ap - da/1024
        bup[2*e + par]     = bu;
        if (lane == 0) {                                  // pre entry (k=32)
            const int e2 = q * KENT + 32;
            fdp[4*e2 + par] = vf;   fdp[4*e2 + 2 + par] = 0.0f;
            adp[4*e2 + par] = 0.0f; adp[4*e2 + 2 + par] = a;
            bup[2*e2 + par] = bu;
        }
        if (lane == 31) {                                 // post entry (k=33)
            const int e3 = q * KENT + 33;
            fdp[4*e3 + par] = vf;   fdp[4*e3 + 2 + par] = 0.0f;
            adp[4*e3 + par] = 0.0f; adp[4*e3 + 2 + par] = a;
            bup[2*e3 + par] = bu;
        }
    }
    __syncthreads();

    // ---- per-thread sample constants: k and c1[s] only ----
    const int i0 = blockIdx.x * SAMP_CHUNK + tid * SPT;
    int k;
    float c1[SPT];
    if (i0 < 256) {
        k = 32;
#pragma unroll
        for (int s = 0; s < SPT; ++s) c1[s] = 0.5f * (float)(i0 + s - 255);
    } else if (i0 >= 16128) {
        k = 33;
#pragma unroll
        for (int s = 0; s < SPT; ++s) c1[s] = 0.5f * (float)(i0 + s - 16127);
    } else {
        k = (i0 - 256) >> 9;
        const int m0 = (i0 - 256) & 511;
#pragma unroll
        for (int s = 0; s < SPT; ++s) c1[s] = 0.5f * (float)(m0 + s + 1);
    }

    unsigned long long c1p[SPT], acc2[SPT];
    float accm[SPT];
    unsigned long long a1p, a3p, a5p, a7p, a9p, mgp, nmgp, non;
    PACK2(a1p, SA1, SA1);  PACK2(a3p, SA3, SA3);  PACK2(a5p, SA5, SA5);
    PACK2(a7p, SA7, SA7);  PACK2(a9p, SA9, SA9);
    PACK2(mgp, MAGIC, MAGIC);  PACK2(nmgp, -MAGIC, -MAGIC);
    PACK2(non, -1.0f, -1.0f);
#pragma unroll
    for (int s = 0; s < SPT; ++s) {
        PACK2(c1p[s], c1[s], c1[s]);
        acc2[s] = 0ull;
        accm[s] = 0.0f;
    }

    // ---- phase 2: hybrid main loop (poly pair + mufu pair per iteration) ----
    const float4* fk = &s_fd[k];
    const float4* ak = &s_ad[k];
    const float2* bk = &s_bu[k];
#pragma unroll 2
    for (int q = 0; q < HPAIRS; ++q) {
        // poly pair q (cycles)
        const float4 fdP = fk[q * KENT];
        const float4 adP = ak[q * KENT];
        const float2 buP = bk[q * KENT];
        // mufu pair q+8 (radians)
        const float4 fdM = fk[(q + HPAIRS) * KENT];
        const float4 adM = ak[(q + HPAIRS) * KENT];
        const float2 buM = bk[(q + HPAIRS) * KENT];

        unsigned long long fp2, df2, dc2, aa2, bu2;
        PACK2(fp2, fdP.x, fdP.y);
        PACK2(df2, fdP.z, fdP.w);
        PACK2(dc2, adP.x, adP.y);
        PACK2(aa2, adP.z, adP.w);
        PACK2(bu2, buP.x, buP.y);

#pragma unroll
        for (int s = 0; s < SPT; ++s) {
            // --- poly (FMA pipe, packed 2 osc) ---
            unsigned long long t, u, tm, ri, r, z, h, sv, amp;
            FMA2(t,  c1p[s], df2, fp2);
            FMA2(u,  c1p[s], t,   bu2);
            ADD2(tm, u, mgp);
            ADD2(ri, tm, nmgp);
            FMA2(r,  ri, non, u);          // r = u - rint(u), exact
            MUL2(z,  r, r);
            FMA2(h,  z, a9p, a7p);
            FMA2(h,  h, z, a5p);
            FMA2(h,  h, z, a3p);
            FMA2(h,  h, z, a1p);
            MUL2(sv, h, r);
            FMA2(amp, c1p[s], dc2, aa2);
            FMA2(acc2[s], sv, amp, acc2[s]);

            // --- mufu (XU pipe, 2 scalar osc) ---
            const float tE = fmaf(c1[s], fdM.z, fdM.x);
            const float QE = fmaf(c1[s], tE, buM.x);
            const float svE = __sinf(QE);
            const float amE = fmaf(c1[s], adM.x, adM.z);
            const float tO = fmaf(c1[s], fdM.w, fdM.y);
            const float QO = fmaf(c1[s], tO, buM.y);
            const float svO = __sinf(QO);
            const float amO = fmaf(c1[s], adM.y, adM.w);
            accm[s] = fmaf(svE, amE, accm[s]);
            accm[s] = fmaf(svO, amO, accm[s]);
        }
    }

    float acc[SPT];
#pragma unroll
    for (int s = 0; s < SPT; ++s) {
        float lo, hi;
        UNPACK2(lo, hi, acc2[s]);
        acc[s] = (lo + hi) + accm[s];
    }
    *reinterpret_cast<float4*>(&g_scratch[blockIdx.y * N_SAMP + i0]) =
        make_float4(acc[0], acc[1], acc[2], acc[3]);

    // ---- phase 3: last block per column reduces (fixed order = deterministic) ----
    __threadfence();
    __syncthreads();
    if (tid == 0)
        s_old = atomicInc(&g_cnt[blockIdx.x], N_OSC_BLK - 1);   // wraps 63 -> 0
    __syncthreads();

    if (s_old == N_OSC_BLK - 1) {
        __threadfence();
        const int j0 = blockIdx.x * SAMP_CHUNK + tid * 4;
        float4 a0 = make_float4(0.f, 0.f, 0.f, 0.f);
        float4 a1 = a0;
#pragma unroll
        for (int b = 0; b < N_OSC_BLK; b += 2) {
            const float4 v0 = *reinterpret_cast<const float4*>(&g_scratch[(b + 0) * N_SAMP + j0]);
            const float4 v1 = *reinterpret_cast<const float4*>(&g_scratch[(b + 1) * N_SAMP + j0]);
            a0.x += v0.x; a0.y += v0.y; a0.z += v0.z; a0.w += v0.w;
            a1.x += v1.x; a1.y += v1.y; a1.z += v1.z; a1.w += v1.w;
        }
        const float sc = 1.0f / (float)N_OSC;
        *reinterpret_cast<float4*>(&out[j0]) = make_float4(
            (a0.x + a1.x) * sc, (a0.y + a1.y) * sc,
            (a0.z + a1.z) * sc, (a0.w + a1.w) * sc);
    }
}

extern "C" void kernel_launch(void* const* d_in, const int* in_sizes, int n_in,
                              void* d_out, int out_size) {
    const float* latent = (const float*)d_in[n_in - 1];
    for (int i = 0; i < n_in; ++i) {
        if (in_sizes[i] == 2 * HALF) { latent = (const float*)d_in[i]; break; }
    }
    float* out = (float*)d_out;

    dim3 grid(N_SAMP_BLK, N_OSC_BLK);                       // 16 x 64 = 1024 blocks
    osc_kernel<<<grid, THREADS>>>(latent, out);
}

// round 14
// speedup vs baseline: 1.1892x; 1.0723x over previous
#include <cuda_runtime.h>
#include <math.h>

constexpr int N_OSC  = 2048;
constexpr int N_SAMP = 16384;
constexpr int LAT    = 32;
constexpr int HALF   = N_OSC * LAT;               // 65536

constexpr int OSC_CHUNK  = 32;
constexpr int N_MUFU     = 24;                     // osc 0..23  -> __sinf (XU pipe)
                                                   // osc 24..31 -> poly (FMA pipe)
constexpr int KENT       = LAT + 2;                // 32 segs + pre(32) + post(33)
constexpr int SAMP_CHUNK = 1024;
constexpr int THREADS    = 256;
constexpr int SPT        = 4;
constexpr int N_OSC_BLK  = N_OSC / OSC_CHUNK;      // 64
constexpr int N_SAMP_BLK = N_SAMP / SAMP_CHUNK;    // 16

__device__ float    g_scratch[N_OSC_BLK * N_SAMP];   // 4 MB partials
__device__ unsigned g_cnt[N_SAMP_BLK];               // wraps 63->0: replay-safe

// sin(2*pi*r), r in [-0.5,0.5]: degree-9 odd poly (max err ~3e-5, validated R12)
constexpr float SA1 =  6.2831008f;
constexpr float SA3 = -41.332240f;
constexpr float SA5 =  81.374886f;
constexpr float SA7 = -74.511488f;
constexpr float SA9 =  32.841421f;
constexpr float MAGIC   = 12582912.0f;               // 1.5 * 2^23
constexpr float TWOPI_F = 6.28318530717958648f;

// -----------------------------------------------------------------------------
// HYBRID x=0.25, SEQUENTIAL sub-loops (R13 lesson: interleaved fat body kills
// both pipes; sequential lean bodies + warp drift overlap them instead).
//   loop A: 24 oscillators, __sinf         -> saturates MUFU at ~0.75x rate
//   loop B:  8 oscillators, scalar poly    -> runs on FMA pipe
// Tables: mufu osc pre-scaled by 2*pi (radians); poly osc in cycles.
// KENT entries per osc include pre(32)/post(33) rows -> branch-free loops.
// -----------------------------------------------------------------------------
__global__ __launch_bounds__(THREADS, 4)
void osc_kernel(const float* __restrict__ latent, float* __restrict__ out) {
    __shared__ float4 s_pk[OSC_CHUNK * KENT];  // (v, dv, dac, apadj)  ~17 KB
    __shared__ float  s_bu[OSC_CHUNK * KENT];  // phase base           ~4.3 KB
    __shared__ unsigned s_old;

    const int tid  = threadIdx.x;
    const int lane = tid & 31;
    const int warp = tid >> 5;
    const int oscBase = blockIdx.y * OSC_CHUNK;

    // ---- phase 0: |latent| passthrough ----
    if (tid < 32) {
        const int idx = ((blockIdx.y * N_SAMP_BLK + blockIdx.x) * 32 + tid) * 4;
        const int src = (idx < HALF) ? (HALF + idx) : (idx - HALF);
        const float4 v = *reinterpret_cast<const float4*>(&latent[src]);
        *reinterpret_cast<float4*>(&out[N_SAMP + idx]) =
            make_float4(fabsf(v.x), fabsf(v.y), fabsf(v.z), fabsf(v.w));
    }

    // ---- phase 1: fp32 warp-scan prologue, 8 warps x 4 oscillators ----
#pragma unroll
    for (int j = 0; j < OSC_CHUNK / 8; ++j) {
        const int o  = warp * (OSC_CHUNK / 8) + j;
        const int go = oscBase + o;
        const float f  = fabsf(latent[(size_t)(N_OSC + go) * LAT + lane]);
        const float a  = fabsf(latent[(size_t)go * LAT + lane]);
        const float fn = __shfl_down_sync(0xffffffffu, f, 1);
        const float an = __shfl_down_sync(0xffffffffu, a, 1);
        const float df = (lane < 31) ? (fn - f) : 0.0f;
        const float da = (lane < 31) ? (an - a) : 0.0f;
        const float t = (lane < 31) ? 256.0f * (f + fn) : 0.0f;
        float sc = t;
#pragma unroll
        for (int d = 1; d < 32; d <<= 1) {
            const float u = __shfl_up_sync(0xffffffffu, sc, d);
            if (lane >= d) sc += u;
        }
        const float f0 = __shfl_sync(0xffffffffu, f, 0);
        const float C  = fmaf(256.0f, f0, sc - t);        // exclusive prefix C_k
        const float r  = fmaf(-2.0f, rintf(0.5f * C), C); // C mod 2, exact
        // mufu oscillators (o < N_MUFU): radians; poly oscillators: cycles
        const float S  = (o < N_MUFU) ? TWOPI_F : 1.0f;
        const float vf = S * f;
        const float dv = S * (df * (1.0f / 512.0f));
        const float bu = S * (0.5f * r);
        const float dac = da * (1.0f / 256.0f);
        const float aa  = fmaf(da, -0.0009765625f, a);    // ap - da/1024
        s_pk[o * KENT + lane] = make_float4(vf, dv, dac, aa);
        s_bu[o * KENT + lane] = bu;
        if (lane == 0) {                                  // pre entry (k=32)
            s_pk[o * KENT + 32] = make_float4(vf, 0.0f, 0.0f, a);
            s_bu[o * KENT + 32] = bu;
        }
        if (lane == 31) {                                 // post entry (k=33)
            s_pk[o * KENT + 33] = make_float4(vf, 0.0f, 0.0f, a);
            s_bu[o * KENT + 33] = bu;
        }
    }
    __syncthreads();

    // ---- per-thread sample constants: k and c1[s] only ----
    const int i0 = blockIdx.x * SAMP_CHUNK + tid * SPT;
    int k;
    float c1[SPT];
    if (i0 < 256) {
        k = 32;
#pragma unroll
        for (int s = 0; s < SPT; ++s) c1[s] = 0.5f * (float)(i0 + s - 255);
    } else if (i0 >= 16128) {
        k = 33;
#pragma unroll
        for (int s = 0; s < SPT; ++s) c1[s] = 0.5f * (float)(i0 + s - 16127);
    } else {
        k = (i0 - 256) >> 9;
        const int m0 = (i0 - 256) & 511;
#pragma unroll
        for (int s = 0; s < SPT; ++s) c1[s] = 0.5f * (float)(m0 + s + 1);
    }

    float acc[SPT] = {0.f, 0.f, 0.f, 0.f};
    const float4* pk = &s_pk[k];
    const float*  bk = &s_bu[k];

    // ---- loop A: 24 mufu oscillators (lean R11 body, XU pipe) ----
#pragma unroll 4
    for (int o = 0; o < N_MUFU; ++o) {
        const float4 p  = pk[o * KENT];                // (v, dv, dac, apadj)
        const float  bq = bk[o * KENT];
#pragma unroll
        for (int s = 0; s < SPT; ++s) {
            const float t   = fmaf(c1[s], p.y, p.x);
            const float Q   = fmaf(c1[s], t, bq);
            const float sv  = __sinf(Q);
            const float amp = fmaf(c1[s], p.z, p.w);
            acc[s] = fmaf(sv, amp, acc[s]);
        }
    }

    // ---- loop B: 8 poly oscillators (scalar, FMA pipe, no MUFU) ----
#pragma unroll 2
    for (int o = N_MUFU; o < OSC_CHUNK; ++o) {
        const float4 p  = pk[o * KENT];
        const float  bq = bk[o * KENT];
#pragma unroll
        for (int s = 0; s < SPT; ++s) {
            const float t  = fmaf(c1[s], p.y, p.x);
            const float u  = fmaf(c1[s], t, bq);       // phase in cycles
            const float ri = (u + MAGIC) - MAGIC;      // rint(u), exact trick
            const float r  = u - ri;                   // in [-0.5, 0.5], exact
            const float z  = r * r;
            float h = fmaf(z, SA9, SA7);
            h = fmaf(h, z, SA5);
            h = fmaf(h, z, SA3);
            h = fmaf(h, z, SA1);
            const float sv  = h * r;
            const float amp = fmaf(c1[s], p.z, p.w);
            acc[s] = fmaf(sv, amp, acc[s]);
        }
    }

    *reinterpret_cast<float4*>(&g_scratch[blockIdx.y * N_SAMP + i0]) =
        make_float4(acc[0], acc[1], acc[2], acc[3]);

    // ---- phase 3: last block per column reduces (fixed order = deterministic) ----
    __threadfence();
    __syncthreads();
    if (tid == 0)
        s_old = atomicInc(&g_cnt[blockIdx.x], N_OSC_BLK - 1);   // wraps 63 -> 0
    __syncthreads();

    if (s_old == N_OSC_BLK - 1) {
        __threadfence();
        const int j0 = blockIdx.x * SAMP_CHUNK + tid * 4;
        float4 a0 = make_float4(0.f, 0.f, 0.f, 0.f);
        float4 a1 = a0;
#pragma unroll
        for (int b = 0; b < N_OSC_BLK; b += 2) {
            const float4 v0 = *reinterpret_cast<const float4*>(&g_scratch[(b + 0) * N_SAMP + j0]);
            const float4 v1 = *reinterpret_cast<const float4*>(&g_scratch[(b + 1) * N_SAMP + j0]);
            a0.x += v0.x; a0.y += v0.y; a0.z += v0.z; a0.w += v0.w;
            a1.x += v1.x; a1.y += v1.y; a1.z += v1.z; a1.w += v1.w;
        }
        const float sc = 1.0f / (float)N_OSC;
        *reinterpret_cast<float4*>(&out[j0]) = make_float4(
            (a0.x + a1.x) * sc, (a0.y + a1.y) * sc,
            (a0.z + a1.z) * sc, (a0.w + a1.w) * sc);
    }
}

extern "C" void kernel_launch(void* const* d_in, const int* in_sizes, int n_in,
                              void* d_out, int out_size) {
    const float* latent = (const float*)d_in[n_in - 1];
    for (int i = 0; i < n_in; ++i) {
        if (in_sizes[i] == 2 * HALF) { latent = (const float*)d_in[i]; break; }
    }
    float* out = (float*)d_out;

    dim3 grid(N_SAMP_BLK, N_OSC_BLK);                       // 16 x 64 = 1024 blocks
    osc_kernel<<<grid, THREADS>>>(latent, out);
}